// round 6
// baseline (speedup 1.0000x reference)
#include <cuda_runtime.h>
#include <cstdint>

// out[b,c,h,w] = image[b,c,h,w] * weight[cam[b],c] + bias[cam[b],c]
// image: [16,3,1024,1024] f32; camera_index: [16] i32; weight/bias: [34,3] f32.
//
// Persistent single-wave kernel: grid = 148 SMs * 3 CTAs = 444 blocks,
// each striding over chunks of TPB*UNROLL = 2048 float4s. A plane is 2^18
// float4s and 2^18 % 2048 == 0, so (b,c) is uniform within each chunk.
// MLP_p1 = 4 independent LDG.128 per thread per chunk iteration.

static constexpr int PLANE4  = 1 << 18;           // float4s per (b,c) plane
static constexpr int TOTAL4  = 16 * 3 * PLANE4;   // 12,582,912
static constexpr int TPB     = 512;
static constexpr int UNROLL  = 4;
static constexpr int CHUNK   = TPB * UNROLL;      // 2048 float4s
static constexpr int NCHUNKS = TOTAL4 / CHUNK;    // 6144
static constexpr int NBLOCKS = 148 * 3;           // one wave (3 CTAs/SM @ 32 regs)

__global__ void __launch_bounds__(TPB) colorcal_kernel(
        const float4* __restrict__ image,
        const int*    __restrict__ cam_idx,
        const float*  __restrict__ weight,
        const float*  __restrict__ bias,
        float4*       __restrict__ out) {
    for (int chunk = blockIdx.x; chunk < NCHUNKS; chunk += NBLOCKS) {
        int base = chunk * CHUNK;

        int plane = base >> 18;           // (b,c) uniform across the chunk
        int c = plane % 3;
        int b = plane / 3;
        int cam = __ldg(&cam_idx[b]);
        float s = __ldg(&weight[cam * 3 + c]);
        float t = __ldg(&bias[cam * 3 + c]);

        int i0 = base + threadIdx.x;

        // Front-batch 4 independent 16B loads (MLP_p1 = 4).
        float4 v[UNROLL];
#pragma unroll
        for (int k = 0; k < UNROLL; k++)
            v[k] = __ldcs(&image[i0 + k * TPB]);

#pragma unroll
        for (int k = 0; k < UNROLL; k++) {
            float4 r;
            r.x = fmaf(v[k].x, s, t);
            r.y = fmaf(v[k].y, s, t);
            r.z = fmaf(v[k].z, s, t);
            r.w = fmaf(v[k].w, s, t);
            __stcs(&out[i0 + k * TPB], r);
        }
    }
}

extern "C" void kernel_launch(void* const* d_in, const int* in_sizes, int n_in,
                              void* d_out, int out_size) {
    const float4* image = (const float4*)d_in[0];
    const int*    cam   = (const int*)d_in[1];
    const float*  w     = (const float*)d_in[2];
    const float*  bse   = (const float*)d_in[3];
    float4*       out   = (float4*)d_out;

    colorcal_kernel<<<NBLOCKS, TPB>>>(image, cam, w, bse, out);
}

// round 7
// speedup vs baseline: 1.1144x; 1.1144x over previous
#include <cuda_runtime.h>
#include <cstdint>

// out[b,c,h,w] = image[b,c,h,w] * weight[cam[b],c] + bias[cam[b],c]
// image: [16,3,1024,1024] f32; camera_index: [16] i32; weight/bias: [34,3] f32.
//
// Roofline kernel (confirmed over R3-R6): flat grid, TPB=512, UNROLL=4.
// Chunk = 2048 float4s per block; plane = 2^18 float4s, 2^18 % 2048 == 0 ->
// (b,c) uniform per block. 4 independent LDG.128 per thread (MLP_p1=4),
// streaming cache hints. Measured 6.10 TB/s — the mixed R+W HBM ceiling;
// persistent-grid and higher-MLP variants were neutral or worse.

static constexpr int PLANE4  = 1 << 18;           // float4s per (b,c) plane
static constexpr int TOTAL4  = 16 * 3 * PLANE4;   // 12,582,912
static constexpr int TPB     = 512;
static constexpr int UNROLL  = 4;
static constexpr int CHUNK   = TPB * UNROLL;      // 2048 float4s per block
static constexpr int NBLOCKS = TOTAL4 / CHUNK;    // 6144

__global__ void __launch_bounds__(TPB) colorcal_kernel(
        const float4* __restrict__ image,
        const int*    __restrict__ cam_idx,
        const float*  __restrict__ weight,
        const float*  __restrict__ bias,
        float4*       __restrict__ out) {
    int base = blockIdx.x * CHUNK;

    int plane = base >> 18;           // (b,c) uniform across the block
    int c = plane % 3;
    int b = plane / 3;
    int cam = __ldg(&cam_idx[b]);
    float s = __ldg(&weight[cam * 3 + c]);
    float t = __ldg(&bias[cam * 3 + c]);

    int i0 = base + threadIdx.x;

    // Front-batch 4 independent 16B loads (MLP_p1 = 4).
    float4 v[UNROLL];
#pragma unroll
    for (int k = 0; k < UNROLL; k++)
        v[k] = __ldcs(&image[i0 + k * TPB]);

#pragma unroll
    for (int k = 0; k < UNROLL; k++) {
        float4 r;
        r.x = fmaf(v[k].x, s, t);
        r.y = fmaf(v[k].y, s, t);
        r.z = fmaf(v[k].z, s, t);
        r.w = fmaf(v[k].w, s, t);
        __stcs(&out[i0 + k * TPB], r);
    }
}

extern "C" void kernel_launch(void* const* d_in, const int* in_sizes, int n_in,
                              void* d_out, int out_size) {
    const float4* image = (const float4*)d_in[0];
    const int*    cam   = (const int*)d_in[1];
    const float*  w     = (const float*)d_in[2];
    const float*  bse   = (const float*)d_in[3];
    float4*       out   = (float4*)d_out;

    colorcal_kernel<<<NBLOCKS, TPB>>>(image, cam, w, bse, out);
}

// round 8
// speedup vs baseline: 1.1332x; 1.0169x over previous
#include <cuda_runtime.h>
#include <cstdint>

// out[b,c,h,w] = image[b,c,h,w] * weight[cam[b],c] + bias[cam[b],c]
// image: [16,3,1024,1024] f32; camera_index: [16] i32; weight/bias: [34,3] f32.
//
// Max-residency probe: TPB=1024 (2 CTAs/SM -> 64 warps/SM, 100% occ) with
// UNROLL=4 (MLP_p1=4). Chunk = 4096 float4s; plane = 2^18 float4s,
// 2^18 % 4096 == 0 -> (b,c) uniform per block. Grid = 3072.

static constexpr int PLANE4  = 1 << 18;           // float4s per (b,c) plane
static constexpr int TOTAL4  = 16 * 3 * PLANE4;   // 12,582,912
static constexpr int TPB     = 1024;
static constexpr int UNROLL  = 4;
static constexpr int CHUNK   = TPB * UNROLL;      // 4096 float4s per block
static constexpr int NBLOCKS = TOTAL4 / CHUNK;    // 3072

__global__ void __launch_bounds__(TPB) colorcal_kernel(
        const float4* __restrict__ image,
        const int*    __restrict__ cam_idx,
        const float*  __restrict__ weight,
        const float*  __restrict__ bias,
        float4*       __restrict__ out) {
    int base = blockIdx.x * CHUNK;

    int plane = base >> 18;           // (b,c) uniform across the block
    int c = plane % 3;
    int b = plane / 3;
    int cam = __ldg(&cam_idx[b]);
    float s = __ldg(&weight[cam * 3 + c]);
    float t = __ldg(&bias[cam * 3 + c]);

    int i0 = base + threadIdx.x;

    // Front-batch 4 independent 16B loads (MLP_p1 = 4).
    float4 v[UNROLL];
#pragma unroll
    for (int k = 0; k < UNROLL; k++)
        v[k] = __ldcs(&image[i0 + k * TPB]);

#pragma unroll
    for (int k = 0; k < UNROLL; k++) {
        float4 r;
        r.x = fmaf(v[k].x, s, t);
        r.y = fmaf(v[k].y, s, t);
        r.z = fmaf(v[k].z, s, t);
        r.w = fmaf(v[k].w, s, t);
        __stcs(&out[i0 + k * TPB], r);
    }
}

extern "C" void kernel_launch(void* const* d_in, const int* in_sizes, int n_in,
                              void* d_out, int out_size) {
    const float4* image = (const float4*)d_in[0];
    const int*    cam   = (const int*)d_in[1];
    const float*  w     = (const float*)d_in[2];
    const float*  bse   = (const float*)d_in[3];
    float4*       out   = (float4*)d_out;

    colorcal_kernel<<<NBLOCKS, TPB>>>(image, cam, w, bse, out);
}